// round 4
// baseline (speedup 1.0000x reference)
#include <cuda_runtime.h>
#include <cuda_bf16.h>
#include <cstdint>

// Problem constants (fixed by the dataset)
#define B_DIM 32
#define L_DIM 256
#define H_DIM 512
#define H4    (H_DIM / 4)      // 128 float4 per row
#define T_MAX (L_DIM * 15)     // 3840: max possible total duration
#define FPB   16               // frames per expand block (divides 32 -> no tail)
#define KUNR  8                // frames per thread (MLP)

// Scratch: frame -> SOURCE ROW index (b*L + idx), or -1 when masked (zero-fill)
__device__ int g_row[B_DIM * T_MAX];

// ---------------------------------------------------------------------------
// Kernel 1: per-batch cumsum of durations, scatter frame->source-row map,
// fill tail with -1, write mask floats directly into d_out's mask region.
// One block per batch, 256 threads (== L).
// ---------------------------------------------------------------------------
__global__ void k_prep(const int* __restrict__ dur,
                       float* __restrict__ mask_out,   // d_out + B*T*H
                       int T) {
    const int b = blockIdx.x;
    const int i = threadIdx.x;          // encoder position 0..255
    __shared__ int s_warp[8];

    int d = dur[b * L_DIM + i];

    // Warp inclusive scan
    int v = d;
    const int lane = i & 31;
    const int wid  = i >> 5;
    #pragma unroll
    for (int off = 1; off < 32; off <<= 1) {
        int n = __shfl_up_sync(0xffffffffu, v, off);
        if (lane >= off) v += n;
    }
    if (lane == 31) s_warp[wid] = v;
    __syncthreads();
    if (wid == 0) {
        int w = (lane < 8) ? s_warp[lane] : 0;
        #pragma unroll
        for (int off = 1; off < 8; off <<= 1) {
            int n = __shfl_up_sync(0xffffffffu, w, off);
            if (lane >= off) w += n;
        }
        if (lane < 8) s_warp[lane] = w;
    }
    __syncthreads();

    const int incl  = v + ((wid > 0) ? s_warp[wid - 1] : 0);
    const int total = s_warp[7];
    const int start = incl - d;

    int* gr = g_row + b * T;
    const int srcrow = b * L_DIM + i;   // precomputed source row for expand

    for (int k = 0; k < d; ++k)
        gr[start + k] = srcrow;

    for (int t = total + i; t < T; t += L_DIM)
        gr[t] = -1;

    float* mrow = mask_out + (size_t)b * T;
    for (int t = i; t < T; t += L_DIM)
        mrow[t] = (t < total) ? 1.0f : 0.0f;
}

// ---------------------------------------------------------------------------
// Kernel 2: gather/expand with MLP=8 per thread, no bounds checks.
// 256 threads/block, FPB=16 frames/block:
//   c    = tid & 127   (float4 column in the 512-float row)
//   fsub = tid >> 7    (0..1)
//   thread covers frames fsub + 2k, k=0..7.
// nbt = 32*T is always divisible by FPB=16, so the grid tiles exactly.
// g_row loads are warp-uniform (whole warp shares fsub) -> broadcast.
// ---------------------------------------------------------------------------
__global__ void __launch_bounds__(256, 2)
k_expand(const float4* __restrict__ x4,
         float4* __restrict__ out4) {
    const int tid  = threadIdx.x;
    const int c    = tid & (H4 - 1);
    const int fsub = tid >> 7;                 // 0 or 1
    const int bt0  = blockIdx.x * FPB + fsub;

    int rows[KUNR];
    #pragma unroll
    for (int k = 0; k < KUNR; ++k)
        rows[k] = __ldg(&g_row[bt0 + 2 * k]);

    float4 vals[KUNR];
    #pragma unroll
    for (int k = 0; k < KUNR; ++k) {
        if (rows[k] >= 0)
            vals[k] = __ldg(&x4[(size_t)rows[k] * H4 + c]);
        else
            vals[k] = make_float4(0.f, 0.f, 0.f, 0.f);
    }

    #pragma unroll
    for (int k = 0; k < KUNR; ++k)
        out4[(size_t)(bt0 + 2 * k) * H4 + c] = vals[k];
}

// ---------------------------------------------------------------------------
extern "C" void kernel_launch(void* const* d_in, const int* in_sizes, int n_in,
                              void* d_out, int out_size) {
    const float* x   = (const float*)d_in[0];   // (B, L, H) float32
    const int*   dur = (const int*)d_in[1];     // (B, L)    int32

    // out_size = B*T*(H+1)  =>  T
    const int T   = out_size / (B_DIM * (H_DIM + 1));
    const int nbt = B_DIM * T;

    float* out      = (float*)d_out;                      // (B, T, H)
    float* mask_out = out + (size_t)nbt * H_DIM;          // (B, T)

    k_prep<<<B_DIM, L_DIM>>>(dur, mask_out, T);
    k_expand<<<nbt / FPB, 256>>>((const float4*)x, (float4*)out);

    (void)in_sizes; (void)n_in;
}